// round 8
// baseline (speedup 1.0000x reference)
#include <cuda_runtime.h>
#include <cuda_bf16.h>
#include <math.h>
#include <stdint.h>

#define BB 2
#define LL 2048
#define HH 8
#define DH 64
#define HID 512
#define QKVP 3584
#define VP 2560
#define TOK (BB*LL)

// ---- static scratch ----
__device__ float g_scan[BB * 64 * LL];                  // scan channels [b][c][l]
__device__ __nv_bfloat16 g_A1h[(size_t)TOK * HID];
__device__ __nv_bfloat16 g_A1l[(size_t)TOK * HID];
__device__ __nv_bfloat16 g_B1h[(size_t)QKVP * HID];
__device__ __nv_bfloat16 g_B1l[(size_t)QKVP * HID];
__device__ __nv_bfloat16 g_A2h[(size_t)TOK * VP];
__device__ __nv_bfloat16 g_A2l[(size_t)TOK * VP];
__device__ __nv_bfloat16 g_B2h[(size_t)HID * VP];
__device__ __nv_bfloat16 g_B2l[(size_t)HID * VP];
#define QKV_ELEMS ((size_t)BB * HH * LL * DH)
__device__ __nv_bfloat16 g_Qh[QKV_ELEMS];
__device__ __nv_bfloat16 g_Ql[QKV_ELEMS];
__device__ __nv_bfloat16 g_Kh[QKV_ELEMS];
__device__ __nv_bfloat16 g_Kl[QKV_ELEMS];
__device__ __nv_bfloat16 g_Vh[QKV_ELEMS];
__device__ __nv_bfloat16 g_Vl[QKV_ELEMS];

// ============================================================
// helpers
// ============================================================
__device__ __forceinline__ uint32_t smem_u32(const void* p) {
    uint32_t a;
    asm("{ .reg .u64 t; cvta.to.shared.u64 t, %1; cvt.u32.u64 %0, t; }" : "=r"(a) : "l"(p));
    return a;
}
__device__ __forceinline__ void ldsm_x4(uint32_t addr, uint32_t* r) {
    asm volatile("ldmatrix.sync.aligned.m8n8.x4.shared.b16 {%0,%1,%2,%3}, [%4];"
                 : "=r"(r[0]), "=r"(r[1]), "=r"(r[2]), "=r"(r[3]) : "r"(addr));
}
__device__ __forceinline__ void ldsm_x4_t(uint32_t addr, uint32_t* r) {
    asm volatile("ldmatrix.sync.aligned.m8n8.x4.trans.shared.b16 {%0,%1,%2,%3}, [%4];"
                 : "=r"(r[0]), "=r"(r[1]), "=r"(r[2]), "=r"(r[3]) : "r"(addr));
}
__device__ __forceinline__ void mma_bf16(float* c, const uint32_t* a, uint32_t b0, uint32_t b1) {
    asm volatile("mma.sync.aligned.m16n8k16.row.col.f32.bf16.bf16.f32 "
                 "{%0,%1,%2,%3}, {%4,%5,%6,%7}, {%8,%9}, {%0,%1,%2,%3};"
                 : "+f"(c[0]), "+f"(c[1]), "+f"(c[2]), "+f"(c[3])
                 : "r"(a[0]), "r"(a[1]), "r"(a[2]), "r"(a[3]), "r"(b0), "r"(b1));
}
__device__ __forceinline__ uint32_t bf2bits(__nv_bfloat162 v) {
    return *reinterpret_cast<uint32_t*>(&v);
}
__device__ __forceinline__ void store_split2(__nv_bfloat16* dh, __nv_bfloat16* dl,
                                             size_t off, float v0, float v1) {
    __nv_bfloat162 hp = __floats2bfloat162_rn(v0, v1);
    __nv_bfloat162 lp = __floats2bfloat162_rn(v0 - __low2float(hp), v1 - __high2float(hp));
    *reinterpret_cast<__nv_bfloat162*>(dh + off) = hp;
    *reinterpret_cast<__nv_bfloat162*>(dl + off) = lp;
}
__device__ __forceinline__ void store_split4(__nv_bfloat16* dh, __nv_bfloat16* dl,
                                             size_t off, float4 v) {
    store_split2(dh, dl, off, v.x, v.y);
    store_split2(dh, dl, off + 2, v.z, v.w);
}

// fused qkv/gelu store for gemm1 epilogue (gc pairs never cross a 64 boundary)
__device__ __forceinline__ void qkvp_store(int gr, int gc, float v0, float v1) {
    if (gc < 1536) {
        int part = gc >> 9;
        int rem = gc & 511;
        int h = rem >> 6, d = rem & 63;
        int bb_ = gr >> 11, l = gr & 2047;
        size_t off = (((size_t)(bb_ * 8 + h)) * LL + l) * 64 + d;
        if (part == 0)      store_split2(g_Qh, g_Ql, off, v0, v1);
        else if (part == 1) store_split2(g_Kh, g_Kl, off, v0, v1);
        else                store_split2(g_Vh, g_Vl, off, v0, v1);
    } else {
        float g0 = v0 * normcdff(v0);
        float g1 = v1 * normcdff(v1);
        size_t off = (size_t)gr * VP + 512 + (gc - 1536);
        store_split2(g_A2h, g_A2l, off, g0, g1);
    }
}

// ============================================================
// 1) LayerNorm + feature scatter (writes A1 hi/lo + scan buffer)
// ============================================================
__global__ __launch_bounds__(128) void ln_kernel(const float* __restrict__ x,
                                                 const float* __restrict__ gamma,
                                                 const float* __restrict__ beta)
{
    int tok = blockIdx.x;
    int b = tok / LL, l = tok % LL;
    int t = threadIdx.x;

    float4 v = reinterpret_cast<const float4*>(x + (size_t)tok * HID)[t];
    float s  = v.x + v.y + v.z + v.w;
    float s2 = v.x*v.x + v.y*v.y + v.z*v.z + v.w*v.w;
    #pragma unroll
    for (int o = 16; o; o >>= 1) {
        s  += __shfl_xor_sync(0xffffffffu, s,  o);
        s2 += __shfl_xor_sync(0xffffffffu, s2, o);
    }
    __shared__ float red[8];
    __shared__ float stats[2];
    int w = t >> 5;
    if ((t & 31) == 0) { red[w] = s; red[4 + w] = s2; }
    __syncthreads();
    if (t == 0) {
        float ts  = red[0] + red[1] + red[2] + red[3];
        float ts2 = red[4] + red[5] + red[6] + red[7];
        float mu  = ts * (1.f / HID);
        float var = ts2 * (1.f / HID) - mu * mu;
        stats[0] = mu;
        stats[1] = rsqrtf(var + 1e-5f);
    }
    __syncthreads();
    float mu = stats[0], rstd = stats[1];

    float4 g  = reinterpret_cast<const float4*>(gamma)[t];
    float4 be = reinterpret_cast<const float4*>(beta)[t];
    float4 xn;
    xn.x = (v.x - mu) * rstd * g.x + be.x;
    xn.y = (v.y - mu) * rstd * g.y + be.y;
    xn.z = (v.z - mu) * rstd * g.z + be.z;
    xn.w = (v.w - mu) * rstd * g.w + be.w;

    int c0 = t * 4;
    if (c0 < 320) {
        store_split4(g_A1h, g_A1l, (size_t)tok * HID + c0, xn);
    } else if (c0 < 384) {
        int cc = c0 - 320;
        g_scan[((size_t)b * 64 + cc + 0) * LL + l] = xn.x;
        g_scan[((size_t)b * 64 + cc + 1) * LL + l] = xn.y;
        g_scan[((size_t)b * 64 + cc + 2) * LL + l] = xn.z;
        g_scan[((size_t)b * 64 + cc + 3) * LL + l] = xn.w;
    } else if (c0 < 448) {
        if (l + 1 < LL)
            store_split4(g_A1h, g_A1l, (size_t)(tok + 1) * HID + c0, xn);
        if (l == 0) {
            float4 z = make_float4(0.f, 0.f, 0.f, 0.f);
            store_split4(g_A1h, g_A1l, (size_t)tok * HID + c0, z);
        }
    } else {
        if (l + 2 < LL)
            store_split4(g_A1h, g_A1l, (size_t)(tok + 2) * HID + c0, xn);
        if (l == 0) {
            float4 z = make_float4(0.f, 0.f, 0.f, 0.f);
            store_split4(g_A1h, g_A1l, (size_t)tok * HID + c0, z);
            store_split4(g_A1h, g_A1l, (size_t)(tok + 1) * HID + c0, z);
        }
    }
}

// ============================================================
// 2) cumlogsumexp block scan: one block per (b, channel)
// ============================================================
__global__ __launch_bounds__(256) void scan_kernel2()
{
    int bc = blockIdx.x;               // 0..127 = b*64 + c
    int b = bc >> 6, c = bc & 63;
    const float* src = g_scan + (size_t)bc * LL;
    int t = threadIdx.x, lane = t & 31, w = t >> 5;

    float4 u0 = *reinterpret_cast<const float4*>(src + t * 8);
    float4 u1 = *reinterpret_cast<const float4*>(src + t * 8 + 4);
    float v[8] = {u0.x * 5.f, u0.y * 5.f, u0.z * 5.f, u0.w * 5.f,
                  u1.x * 5.f, u1.y * 5.f, u1.z * 5.f, u1.w * 5.f};

    // block max
    float mx = v[0];
    #pragma unroll
    for (int i = 1; i < 8; i++) mx = fmaxf(mx, v[i]);
    #pragma unroll
    for (int o = 16; o; o >>= 1) mx = fmaxf(mx, __shfl_xor_sync(0xffffffffu, mx, o));
    __shared__ float wred[8];
    __shared__ float Msh;
    if (lane == 0) wred[w] = mx;
    __syncthreads();
    if (t == 0) {
        float m = wred[0];
        #pragma unroll
        for (int i = 1; i < 8; i++) m = fmaxf(m, wred[i]);
        Msh = m;
    }
    __syncthreads();
    float M = Msh;

    // exp + thread sum
    float e[8], tsum = 0.f;
    #pragma unroll
    for (int i = 0; i < 8; i++) { e[i] = __expf(v[i] - M); tsum += e[i]; }

    // warp inclusive scan of thread sums
    float ws = tsum;
    #pragma unroll
    for (int o = 1; o < 32; o <<= 1) {
        float n = __shfl_up_sync(0xffffffffu, ws, o);
        if (lane >= o) ws += n;
    }
    __shared__ float wq[8];
    if (lane == 31) wq[w] = ws;
    __syncthreads();
    if (t < 8) {
        float x2 = wq[t];
        #pragma unroll
        for (int o = 1; o < 8; o <<= 1) {
            float n = __shfl_up_sync(0xffu, x2, o);
            if (t >= o) x2 += n;
        }
        wq[t] = x2;
    }
    __syncthreads();
    float run = ws - tsum + (w > 0 ? wq[w - 1] : 0.f);

    int l0 = t * 8;
    #pragma unroll
    for (int i = 0; i < 8; i++) {
        run += e[i];
        float val = (M + __logf(run)) * 0.2f;
        __nv_bfloat16 hh = __float2bfloat16(val);
        __nv_bfloat16 ll = __float2bfloat16(val - __bfloat162float(hh));
        size_t off = ((size_t)(b * LL + l0 + i)) * HID + 320 + c;
        g_A1h[off] = hh;
        g_A1l[off] = ll;
    }
}

// ============================================================
// 3) transpose + split: W[K][N] fp32 -> T[N][K] hi/lo bf16
// ============================================================
__global__ __launch_bounds__(256) void transcvt_kernel(const float* __restrict__ W,
                                                       __nv_bfloat16* __restrict__ Th,
                                                       __nv_bfloat16* __restrict__ Tl,
                                                       int K, int N)
{
    __shared__ float tile[32][33];
    int n0 = blockIdx.x * 32, k0 = blockIdx.y * 32;
    int tx = threadIdx.x & 31, ty = threadIdx.x >> 5;
    for (int j = ty; j < 32; j += 8)
        tile[j][tx] = W[(size_t)(k0 + j) * N + n0 + tx];
    __syncthreads();
    for (int j = ty; j < 32; j += 8) {
        float v = tile[tx][j];
        __nv_bfloat16 h = __float2bfloat16(v);
        __nv_bfloat16 l = __float2bfloat16(v - __bfloat162float(h));
        Th[(size_t)(n0 + j) * K + k0 + tx] = h;
        Tl[(size_t)(n0 + j) * K + k0 + tx] = l;
    }
}

// ============================================================
// 4) HMMA bf16x3 GEMM, MODE 0 = plain C+bias, MODE 1 = fused qkv/gelu
// ============================================================
#define PADR 40
#define MATB (128 * PADR * 2)
#define BUFB (4 * MATB)
#define GEMM_SMEM (2 * BUFB)

template <int MODE>
__global__ __launch_bounds__(256) void gemm_tc(const __nv_bfloat16* __restrict__ Ah,
                                               const __nv_bfloat16* __restrict__ Al,
                                               const __nv_bfloat16* __restrict__ Bh,
                                               const __nv_bfloat16* __restrict__ Bl,
                                               const float* __restrict__ bias,
                                               float* __restrict__ C,
                                               int M, int N, int K)
{
    extern __shared__ char sm[];
    uint32_t sb = smem_u32(sm);
    int t = threadIdx.x, lane = t & 31, wid = t >> 5;
    int wm = wid >> 2, wc = wid & 3;
    int m0 = blockIdx.y * 128, n0 = blockIdx.x * 128;

    uint32_t aoff[4], boff[2];
    #pragma unroll
    for (int i = 0; i < 4; i++)
        aoff[i] = ((wm * 64 + i * 16 + (lane & 15)) * PADR + (lane >> 4) * 8) * 2;
    #pragma unroll
    for (int jj = 0; jj < 2; jj++)
        boff[jj] = ((wc * 32 + (2 * jj + (lane >> 4)) * 8 + (lane & 7)) * PADR
                    + ((lane >> 3) & 1) * 8) * 2;

    int grow = t >> 1, ghalf = (t & 1) * 16;
    const __nv_bfloat16* pAh = Ah + (size_t)(m0 + grow) * K + ghalf;
    const __nv_bfloat16* pAl = Al + (size_t)(m0 + grow) * K + ghalf;
    const __nv_bfloat16* pBh = Bh + (size_t)(n0 + grow) * K + ghalf;
    const __nv_bfloat16* pBl = Bl + (size_t)(n0 + grow) * K + ghalf;
    uint32_t so0 = (grow * PADR + ghalf) * 2;
    uint32_t so1 = so0 + 16;

    float acc[4][4][4];
    #pragma unroll
    for (int i = 0; i < 4; i++)
        #pragma unroll
        for (int j = 0; j < 4; j++)
            #pragma unroll
            for (int q = 0; q < 4; q++) acc[i][j][q] = 0.f;

    const int nC = K / 32;

    {
        char* b = sm;
        *reinterpret_cast<uint4*>(b + so0)            = *reinterpret_cast<const uint4*>(pAh);
        *reinterpret_cast<uint4*>(b + so1)            = *reinterpret_cast<const uint4*>(pAh + 8);
        *reinterpret_cast<uint4*>(b + MATB + so0)     = *reinterpret_cast<const uint4*>(pAl);
        *reinterpret_cast<uint4*>(b + MATB + so1)     = *reinterpret_cast<const uint4*>(pAl + 8);
        *reinterpret_cast<uint4*>(b + 2*MATB + so0)   = *reinterpret_cast<const uint4*>(pBh);
        *reinterpret_cast<uint4*>(b + 2*MATB + so1)   = *reinterpret_cast<const uint4*>(pBh + 8);
        *reinterpret_cast<uint4*>(b + 3*MATB + so0)   = *reinterpret_cast<const uint4*>(pBl);
        *reinterpret_cast<uint4*>(b + 3*MATB + so1)   = *reinterpret_cast<const uint4*>(pBl + 8);
    }
    __syncthreads();

    for (int c = 0; c < nC; c++) {
        uint4 f0, f1, f2, f3, f4, f5, f6, f7;
        if (c + 1 < nC) {
            int ko = (c + 1) * 32;
            f0 = *reinterpret_cast<const uint4*>(pAh + ko);
            f1 = *reinterpret_cast<const uint4*>(pAh + ko + 8);
            f2 = *reinterpret_cast<const uint4*>(pAl + ko);
            f3 = *reinterpret_cast<const uint4*>(pAl + ko + 8);
            f4 = *reinterpret_cast<const uint4*>(pBh + ko);
            f5 = *reinterpret_cast<const uint4*>(pBh + ko + 8);
            f6 = *reinterpret_cast<const uint4*>(pBl + ko);
            f7 = *reinterpret_cast<const uint4*>(pBl + ko + 8);
        }

        uint32_t base = sb + (c & 1) * BUFB;
        #pragma unroll
        for (int ks = 0; ks < 2; ks++) {
            uint32_t ah[4][4], alr[4][4], bh[2][4], bl[2][4];
            #pragma unroll
            for (int i = 0; i < 4; i++) ldsm_x4(base + aoff[i] + ks * 32, ah[i]);
            #pragma unroll
            for (int i = 0; i < 4; i++) ldsm_x4(base + MATB + aoff[i] + ks * 32, alr[i]);
            #pragma unroll
            for (int jj = 0; jj < 2; jj++) ldsm_x4(base + 2*MATB + boff[jj] + ks * 32, bh[jj]);
            #pragma unroll
            for (int jj = 0; jj < 2; jj++) ldsm_x4(base + 3*MATB + boff[jj] + ks * 32, bl[jj]);

            #pragma unroll
            for (int i = 0; i < 4; i++) {
                #pragma unroll
                for (int j = 0; j < 4; j++) {
                    uint32_t b0h = bh[j >> 1][(j & 1) * 2], b1h = bh[j >> 1][(j & 1) * 2 + 1];
                    uint32_t b0l = bl[j >> 1][(j & 1) * 2], b1l = bl[j >> 1][(j & 1) * 2 + 1];
                    mma_bf16(acc[i][j], ah[i],  b0h, b1h);
                    mma_bf16(acc[i][j], ah[i],  b0l, b1l);
                    mma_bf16(acc[i][j], alr[i], b0h, b1h);
                }
            }
        }

        if (c + 1 < nC) {
            char* b = sm + ((c + 1) & 1) * BUFB;
            *reinterpret_cast<uint4*>(b + so0)          = f0;
            *reinterpret_cast<uint4*>(b + so1)          = f1;
            *reinterpret_cast<uint4*>(b + MATB + so0)   = f2;
            *reinterpret_cast<uint4*>(b + MATB + so1)   = f3;
            *reinterpret_cast<uint4*>(b + 2*MATB + so0) = f4;
            *reinterpret_cast<uint4*>(b + 2*MATB + so1) = f5;
            *reinterpret_cast<uint4*>(b + 3*MATB + so0) = f6;
            *reinterpret_cast<uint4*>(b + 3*MATB + so1) = f7;
            __syncthreads();
        }
    }

    int r = lane >> 2, cp = (lane & 3) * 2;
    #pragma unroll
    for (int i = 0; i < 4; i++) {
        int gr = m0 + wm * 64 + i * 16 + r;
        #pragma unroll
        for (int j = 0; j < 4; j++) {
            int gc = n0 + wc * 32 + j * 8 + cp;
            if (MODE == 0) {
                float b0 = bias ? bias[gc] : 0.f;
                float b1 = bias ? bias[gc + 1] : 0.f;
                float2 v0 = make_float2(acc[i][j][0] + b0, acc[i][j][1] + b1);
                float2 v1 = make_float2(acc[i][j][2] + b0, acc[i][j][3] + b1);
                *reinterpret_cast<float2*>(C + (size_t)gr * N + gc) = v0;
                *reinterpret_cast<float2*>(C + (size_t)(gr + 8) * N + gc) = v1;
            } else {
                qkvp_store(gr,     gc, acc[i][j][0], acc[i][j][1]);
                qkvp_store(gr + 8, gc, acc[i][j][2], acc[i][j][3]);
            }
        }
    }
}

// ============================================================
// 5) HMMA bf16x3 flash attention (unchanged from round 5)
// ============================================================
#define APADB 144
#define QMAT 18432
#define KMAT 9216

__global__ __launch_bounds__(256) void attn_mma()
{
    __shared__ __align__(16) char smb[2 * QMAT];
    uint32_t sb = smem_u32(smb);
    int qt = (int)gridDim.x - 1 - (int)blockIdx.x;
    int bh = blockIdx.y;
    int b = bh >> 3, hd = bh & 7;
    int q0 = qt * 128;
    int t = threadIdx.x, lane = t & 31, w = t >> 5;
    size_t base = (size_t)bh * LL * 64;

    #pragma unroll
    for (int i = 0; i < 4; i++) {
        int ch = t + i * 256;
        int r = ch >> 3, d0 = (ch & 7) * 8;
        size_t g = base + (size_t)(q0 + r) * 64 + d0;
        *reinterpret_cast<uint4*>(smb + r * APADB + d0 * 2)        = *reinterpret_cast<const uint4*>(g_Qh + g);
        *reinterpret_cast<uint4*>(smb + QMAT + r * APADB + d0 * 2) = *reinterpret_cast<const uint4*>(g_Ql + g);
    }
    __syncthreads();

    uint32_t qfh[4][4], qfl[4][4];
    #pragma unroll
    for (int kc = 0; kc < 4; kc++) {
        uint32_t addr = sb + (w * 16 + (lane & 15)) * APADB + (kc * 16 + (lane >> 4) * 8) * 2;
        ldsm_x4(addr, qfh[kc]);
        ldsm_x4(addr + QMAT, qfl[kc]);
    }
    __syncthreads();

    float oacc[8][4];
    #pragma unroll
    for (int j = 0; j < 8; j++)
        #pragma unroll
        for (int q = 0; q < 4; q++) oacc[j][q] = 0.f;
    float m_run[2] = {-1e30f, -1e30f};
    float l_run[2] = {0.f, 0.f};
    float slope = exp2f(-(float)(hd + 1));
    int rbase = q0 + w * 16 + (lane >> 2);
    int imaxw = q0 + w * 16 + 15;
    int ktmax = 2 * qt + 1;

    for (int kt = 0; kt <= ktmax; kt++) {
        int k0 = kt * 64;
        __syncthreads();
        #pragma unroll
        for (int i = 0; i < 2; i++) {
            int ch = t + i * 256;
            int r = ch >> 3, d0 = (ch & 7) * 8;
            size_t g = base + (size_t)(k0 + r) * 64 + d0;
            uint32_t so = r * APADB + d0 * 2;
            *reinterpret_cast<uint4*>(smb + so)            = *reinterpret_cast<const uint4*>(g_Kh + g);
            *reinterpret_cast<uint4*>(smb + KMAT + so)     = *reinterpret_cast<const uint4*>(g_Kl + g);
            *reinterpret_cast<uint4*>(smb + 2 * KMAT + so) = *reinterpret_cast<const uint4*>(g_Vh + g);
            *reinterpret_cast<uint4*>(smb + 3 * KMAT + so) = *reinterpret_cast<const uint4*>(g_Vl + g);
        }
        __syncthreads();
        if (k0 > imaxw) continue;

        float s[8][4];
        #pragma unroll
        for (int j = 0; j < 8; j++)
            #pragma unroll
            for (int q = 0; q < 4; q++) s[j][q] = 0.f;

        #pragma unroll
        for (int kc = 0; kc < 4; kc++) {
            #pragma unroll
            for (int g = 0; g < 4; g++) {
                uint32_t kh4[4], kl4[4];
                uint32_t addr = sb + (g * 16 + (lane >> 4) * 8 + (lane & 7)) * APADB
                              + (kc * 16 + ((lane >> 3) & 1) * 8) * 2;
                ldsm_x4(addr, kh4);
                ldsm_x4(addr + KMAT, kl4);
                #pragma unroll
                for (int hf = 0; hf < 2; hf++) {
                    int jn = g * 2 + hf;
                    mma_bf16(s[jn], qfh[kc], kh4[hf * 2], kh4[hf * 2 + 1]);
                    mma_bf16(s[jn], qfh[kc], kl4[hf * 2], kl4[hf * 2 + 1]);
                    mma_bf16(s[jn], qfl[kc], kh4[hf * 2], kh4[hf * 2 + 1]);
                }
            }
        }

        float mnew[2] = {m_run[0], m_run[1]};
        #pragma unroll
        for (int jn = 0; jn < 8; jn++) {
            #pragma unroll
            for (int q = 0; q < 4; q++) {
                int hf = q >> 1;
                int i = rbase + hf * 8;
                int j = k0 + jn * 8 + (lane & 3) * 2 + (q & 1);
                float v = s[jn][q] * 0.125f + slope * (float)j;
                if (j > i) v = -1e30f;
                s[jn][q] = v;
                mnew[hf] = fmaxf(mnew[hf], v);
            }
        }
        #pragma unroll
        for (int hf = 0; hf < 2; hf++) {
            mnew[hf] = fmaxf(mnew[hf], __shfl_xor_sync(0xffffffffu, mnew[hf], 1));
            mnew[hf] = fmaxf(mnew[hf], __shfl_xor_sync(0xffffffffu, mnew[hf], 2));
        }
        float sc[2];
        #pragma unroll
        for (int hf = 0; hf < 2; hf++) {
            sc[hf] = __expf(m_run[hf] - mnew[hf]);
            m_run[hf] = mnew[hf];
            l_run[hf] *= sc[hf];
        }
        #pragma unroll
        for (int jn = 0; jn < 8; jn++) {
            #pragma unroll
            for (int q = 0; q < 4; q++) {
                int hf = q >> 1;
                float p = __expf(s[jn][q] - mnew[hf]);
                s[jn][q] = p;
                l_run[hf] += p;
            }
        }
        #pragma unroll
        for (int jn = 0; jn < 8; jn++) {
            #pragma unroll
            for (int q = 0; q < 4; q++) oacc[jn][q] *= sc[q >> 1];
        }

        #pragma unroll
        for (int kc = 0; kc < 4; kc++) {
            uint32_t pah[4], pal[4];
            #pragma unroll
            for (int half = 0; half < 2; half++) {
                #pragma unroll
                for (int sub = 0; sub < 2; sub++) {
                    float a = s[2 * kc + sub][half * 2];
                    float bb = s[2 * kc + sub][half * 2 + 1];
                    __nv_bfloat162 hp = __floats2bfloat162_rn(a, bb);
                    float ra = a - __low2float(hp);
                    float rb = bb - __high2float(hp);
                    __nv_bfloat162 lp = __floats2bfloat162_rn(ra, rb);
                    pah[sub * 2 + half] = bf2bits(hp);
                    pal[sub * 2 + half] = bf2bits(lp);
                }
            }
            #pragma unroll
            for (int g = 0; g < 4; g++) {
                uint32_t vh4[4], vl4[4];
                uint32_t addr = sb + 2 * KMAT
                              + (kc * 16 + ((lane >> 3) & 1) * 8 + (lane & 7)) * APADB
                              + (g * 16 + (lane >> 4) * 8) * 2;
                ldsm_x4_t(addr, vh4);
                ldsm_x4_t(addr + KMAT, vl4);
                #pragma unroll
                for (int hf = 0; hf < 2; hf++) {
                    int dn = g * 2 + hf;
                    mma_bf16(oacc[dn], pah, vh4[hf * 2], vh4[hf * 2 + 1]);
                    mma_bf16(oacc[dn], pah, vl4[hf * 2], vl4[hf * 2 + 1]);
                    mma_bf16(oacc[dn], pal, vh4[hf * 2], vh4[hf * 2 + 1]);
                }
            }
        }
    }

    float inv[2];
    #pragma unroll
    for (int hf = 0; hf < 2; hf++) {
        float lr = l_run[hf];
        lr += __shfl_xor_sync(0xffffffffu, lr, 1);
        lr += __shfl_xor_sync(0xffffffffu, lr, 2);
        inv[hf] = 1.f / lr;
    }
    #pragma unroll
    for (int jn = 0; jn < 8; jn++) {
        int d = hd * 64 + jn * 8 + (lane & 3) * 2;
        #pragma unroll
        for (int hf = 0; hf < 2; hf++) {
            int row = q0 + w * 16 + (lane >> 2) + hf * 8;
            float v0 = oacc[jn][hf * 2] * inv[hf];
            float v1 = oacc[jn][hf * 2 + 1] * inv[hf];
            size_t off = (size_t)(b * LL + row) * VP + d;
            store_split2(g_A2h, g_A2l, off, v0, v1);
        }
    }
}

// ============================================================
// launch
// ============================================================
extern "C" void kernel_launch(void* const* d_in, const int* in_sizes, int n_in,
                              void* d_out, int out_size)
{
    const float* x     = (const float*)d_in[0];
    const float* gamma = (const float*)d_in[1];
    const float* beta  = (const float*)d_in[2];
    const float* w_in  = (const float*)d_in[3];
    const float* w_out = (const float*)d_in[4];
    const float* b_out = (const float*)d_in[5];
    float* out = (float*)d_out;

    __nv_bfloat16 *a1h, *a1l, *b1h, *b1l, *a2h, *a2l, *b2h, *b2l;
    cudaGetSymbolAddress((void**)&a1h, g_A1h);
    cudaGetSymbolAddress((void**)&a1l, g_A1l);
    cudaGetSymbolAddress((void**)&b1h, g_B1h);
    cudaGetSymbolAddress((void**)&b1l, g_B1l);
    cudaGetSymbolAddress((void**)&a2h, g_A2h);
    cudaGetSymbolAddress((void**)&a2l, g_A2l);
    cudaGetSymbolAddress((void**)&b2h, g_B2h);
    cudaGetSymbolAddress((void**)&b2l, g_B2l);

    cudaFuncSetAttribute(gemm_tc<0>, cudaFuncAttributeMaxDynamicSharedMemorySize, GEMM_SMEM);
    cudaFuncSetAttribute(gemm_tc<1>, cudaFuncAttributeMaxDynamicSharedMemorySize, GEMM_SMEM);

    transcvt_kernel<<<dim3(QKVP / 32, HID / 32), 256>>>(w_in, b1h, b1l, HID, QKVP);
    transcvt_kernel<<<dim3(HID / 32, VP / 32), 256>>>(w_out, b2h, b2l, VP, HID);

    ln_kernel<<<TOK, 128>>>(x, gamma, beta);
    scan_kernel2<<<BB * 64, 256>>>();

    gemm_tc<1><<<dim3(QKVP / 128, TOK / 128), 256, GEMM_SMEM>>>(
        a1h, a1l, b1h, b1l, nullptr, nullptr, TOK, QKVP, HID);

    attn_mma<<<dim3(LL / 128, BB * HH), 256>>>();

    gemm_tc<0><<<dim3(HID / 128, TOK / 128), 256, GEMM_SMEM>>>(
        a2h, a2l, b2h, b2l, b_out, out, TOK, HID, VP);
}